// round 4
// baseline (speedup 1.0000x reference)
#include <cuda_runtime.h>
#include <cstdint>

#define BS   4
#define SEQ  128
#define DIM  768
#define HID  768
#define NOUT 2
#define MROWS (BS * SEQ)                    // 512
#define PAIR_TOT (BS * SEQ * SEQ * NOUT)    // 131072

// ---------------- device scratch (no allocation allowed) -------------------
__device__ float g_ha[MROWS * HID];         // a @ W1[:D]
__device__ float g_hb[MROWS * HID];         // b @ W1[D:] + b1
__device__ float g_part[2 * PAIR_TOT];      // per-h-half partial scores

// ---------------------------------------------------------------------------
__device__ __forceinline__ uint32_t smem_u32(const void* p) {
    uint32_t a;
    asm("{ .reg .u64 t; cvta.to.shared.u64 t, %1; cvt.u32.u64 %0, t; }"
        : "=r"(a) : "l"(p));
    return a;
}

__device__ __forceinline__ void cp_async16(uint32_t saddr, const void* gptr) {
    asm volatile("cp.async.cg.shared.global [%0], [%1], 16;"
                 :: "r"(saddr), "l"(gptr) : "memory");
}
__device__ __forceinline__ void cp_commit() {
    asm volatile("cp.async.commit_group;" ::: "memory");
}
template <int N>
__device__ __forceinline__ void cp_wait() {
    asm volatile("cp.async.wait_group %0;" :: "n"(N) : "memory");
}

__device__ __forceinline__ uint32_t f2tf32(float x) {
    uint32_t u;
    asm("cvt.rna.tf32.f32 %0, %1;" : "=r"(u) : "f"(x));
    return u;
}

__device__ __forceinline__ void mma_tf32(float* c, const uint32_t* a,
                                         const uint32_t* b) {
    asm volatile(
        "mma.sync.aligned.m16n8k8.row.col.f32.tf32.tf32.f32 "
        "{%0,%1,%2,%3}, {%4,%5,%6,%7}, {%8,%9}, {%0,%1,%2,%3};"
        : "+f"(c[0]), "+f"(c[1]), "+f"(c[2]), "+f"(c[3])
        : "r"(a[0]), "r"(a[1]), "r"(a[2]), "r"(a[3]), "r"(b[0]), "r"(b[1]));
}

// ---- packed f32x2 helpers (sm_100+ baseline PTX, no 'a' features) ---------
typedef unsigned long long u64;

__device__ __forceinline__ u64 pack2(float lo, float hi) {
    u64 r;
    asm("mov.b64 %0, {%1, %2};" : "=l"(r) : "f"(lo), "f"(hi));
    return r;
}
__device__ __forceinline__ void unpack2(float& lo, float& hi, u64 v) {
    asm("mov.b64 {%0, %1}, %2;" : "=f"(lo), "=f"(hi) : "l"(v));
}
__device__ __forceinline__ u64 add2(u64 a, u64 b) {
    u64 r;
    asm("add.rn.f32x2 %0, %1, %2;" : "=l"(r) : "l"(a), "l"(b));
    return r;
}
__device__ __forceinline__ u64 fma2(u64 a, u64 b, u64 c) {
    u64 r;
    asm("fma.rn.f32x2 %0, %1, %2, %3;" : "=l"(r) : "l"(a), "l"(b), "l"(c));
    return r;
}

// ---------------------------------------------------------------------------
// Kernel 1: projection GEMM via mma.sync tf32.
// z=0: g_ha = a @ W1[0:768];  z=1: g_hb = b @ W1[768:1536] + b1
// CTA tile 64m x 64n, 256 threads (8 warps, warp tile 32x16, 2m x 4n grid),
// K chunk 16, 3-stage cp.async pipeline. Grid (12, 8, 2) = 192 CTAs.
// ---------------------------------------------------------------------------
#define ALD 20
#define BLD 72

__global__ __launch_bounds__(256) void proj_tc(
    const float* __restrict__ a, const float* __restrict__ b,
    const float* __restrict__ W1, const float* __restrict__ b1)
{
    __shared__ float As[3][64 * ALD];
    __shared__ float Bs[3][16 * BLD];

    const int tid = threadIdx.x;
    const int wid = tid >> 5;
    const int lane = tid & 31;
    const int r = lane >> 2;            // 0..7
    const int c = lane & 3;             // 0..3
    const int wm = (wid >> 2) * 32;     // warp m base {0,32}
    const int wn = (wid & 3) * 16;      // warp n base {0,16,32,48}

    const int n0 = blockIdx.x * 64;
    const int m0 = blockIdx.y * 64;
    const int z  = blockIdx.z;

    const float* __restrict__ X = z ? b : a;
    const float* __restrict__ W = W1 + (size_t)z * DIM * HID;

    // load assignments (one cp.async16 each for A and B per thread per chunk)
    const int a_r = tid >> 2;           // 0..63
    const int a_c = (tid & 3) * 4;      // 0..12
    const int b_r = tid >> 4;           // 0..15
    const int b_c = (tid & 15) * 4;     // 0..60

    const uint32_t sA[3] = { smem_u32(As[0]), smem_u32(As[1]), smem_u32(As[2]) };
    const uint32_t sB[3] = { smem_u32(Bs[0]), smem_u32(Bs[1]), smem_u32(Bs[2]) };

    auto ldchunk = [&](int chunk, int s) {
        const int k0 = chunk * 16;
        cp_async16(sA[s] + (uint32_t)(a_r * ALD + a_c) * 4,
                   X + (size_t)(m0 + a_r) * DIM + k0 + a_c);
        cp_async16(sB[s] + (uint32_t)(b_r * BLD + b_c) * 4,
                   W + (size_t)(k0 + b_r) * HID + n0 + b_c);
        cp_commit();
    };

    float acc[2][2][4] = {};

    ldchunk(0, 0);
    ldchunk(1, 1);

    for (int chunk = 0; chunk < 48; chunk++) {
        const int s = chunk % 3;
        if (chunk + 2 < 48) ldchunk(chunk + 2, (chunk + 2) % 3);

        if (chunk < 46)      cp_wait<2>();
        else if (chunk == 46) cp_wait<1>();
        else                  cp_wait<0>();
        __syncthreads();

        const float* Ab = As[s];
        const float* Bb = Bs[s];
        #pragma unroll
        for (int ks = 0; ks < 2; ks++) {
            const int kb = ks * 8;
            uint32_t af[2][4];
            #pragma unroll
            for (int mt = 0; mt < 2; mt++) {
                const float* ap = Ab + (wm + mt * 16 + r) * ALD + kb + c;
                af[mt][0] = f2tf32(ap[0]);
                af[mt][1] = f2tf32(ap[8 * ALD]);
                af[mt][2] = f2tf32(ap[4]);
                af[mt][3] = f2tf32(ap[8 * ALD + 4]);
            }
            uint32_t bf[2][2];
            #pragma unroll
            for (int nt = 0; nt < 2; nt++) {
                const float* bp = Bb + (kb + c) * BLD + wn + nt * 8 + r;
                bf[nt][0] = f2tf32(bp[0]);
                bf[nt][1] = f2tf32(bp[4 * BLD]);
            }
            #pragma unroll
            for (int nt = 0; nt < 2; nt++)
                #pragma unroll
                for (int mt = 0; mt < 2; mt++)
                    mma_tf32(acc[mt][nt], af[mt], bf[nt]);
        }
        __syncthreads();   // all warps done with stage s before it is refilled
    }

    // epilogue: write C (+ b1 for z=1)
    float* __restrict__ outp = z ? g_hb : g_ha;
    #pragma unroll
    for (int mt = 0; mt < 2; mt++) {
        #pragma unroll
        for (int nt = 0; nt < 2; nt++) {
            int m = m0 + wm + mt * 16 + r;
            int n = n0 + wn + nt * 8 + c * 2;
            float2 v0 = make_float2(acc[mt][nt][0], acc[mt][nt][1]);
            float2 v1 = make_float2(acc[mt][nt][2], acc[mt][nt][3]);
            if (z) {
                float2 bb = *(const float2*)&b1[n];
                v0.x += bb.x; v0.y += bb.y;
                v1.x += bb.x; v1.y += bb.y;
            }
            *(float2*)&outp[(size_t)m * HID + n] = v0;
            *(float2*)&outp[(size_t)(m + 8) * HID + n] = v1;
        }
    }
}

// ---------------------------------------------------------------------------
// Kernel 2: pairwise relu + reduce to O=2, packed f32x2 over t-pairs.
// relu(x)*w computed exactly as (x + |x|) * (w/2)  (W2 pre-halved in smem).
// ---------------------------------------------------------------------------
#define HC 64
__global__ __launch_bounds__(256) void pair_kernel(const float* __restrict__ W2)
{
    const int tt = blockIdx.x;
    const int st = blockIdx.y;
    const int zb = blockIdx.z;
    const int batch = zb >> 1;
    const int hh = zb & 1;
    const int h0base = hh * (HID / 2);

    __shared__ float sha[32][HC];           // [s_local][h]
    __shared__ float shT[HC][32];           // [h][t_local]
    __shared__ ulonglong2 swd[HC];          // {(w0/2,w0/2),(w1/2,w1/2)} packed

    const int tid = threadIdx.x;
    const int tq = tid & 15;                // t pair index
    const int sq = tid >> 4;                // s pair index

    const float* __restrict__ hap = g_ha + (size_t)(batch * SEQ + st * 32) * HID;
    const float* __restrict__ hbp = g_hb + (size_t)(batch * SEQ + tt * 32) * HID;

    const int lr = tid >> 3;
    const int lc = (tid & 7) * 8;
    const int tr = tid & 31;
    const int th = (tid >> 5) * 8;

    const u64 ABSM = 0x7FFFFFFF7FFFFFFFull;
    u64 accp[2][2] = {};                    // [s_local 0/1][out 0/1], lanes = t pair

    for (int hc = 0; hc < HID / 2; hc += HC) {
        const int h0 = h0base + hc;

        *(float4*)&sha[lr][lc]     = *(const float4*)&hap[(size_t)lr * HID + h0 + lc];
        *(float4*)&sha[lr][lc + 4] = *(const float4*)&hap[(size_t)lr * HID + h0 + lc + 4];

        float4 v0 = *(const float4*)&hbp[(size_t)tr * HID + h0 + th];
        float4 v1 = *(const float4*)&hbp[(size_t)tr * HID + h0 + th + 4];
        shT[th + 0][tr] = v0.x;  shT[th + 1][tr] = v0.y;
        shT[th + 2][tr] = v0.z;  shT[th + 3][tr] = v0.w;
        shT[th + 4][tr] = v1.x;  shT[th + 5][tr] = v1.y;
        shT[th + 6][tr] = v1.z;  shT[th + 7][tr] = v1.w;

        if (tid < HC) {
            float w0 = 0.5f * W2[(h0 + tid) * 2];
            float w1 = 0.5f * W2[(h0 + tid) * 2 + 1];
            swd[tid] = make_ulonglong2(pack2(w0, w0), pack2(w1, w1));
        }
        __syncthreads();

        #pragma unroll 16
        for (int h = 0; h < HC; h++) {
            float a0 = sha[sq * 2][h];
            float a1 = sha[sq * 2 + 1][h];
            u64 bb = *(const u64*)&shT[h][tq * 2];
            ulonglong2 w = swd[h];

            u64 x0 = add2(pack2(a0, a0), bb);
            u64 x1 = add2(pack2(a1, a1), bb);
            u64 s0 = add2(x0, x0 & ABSM);       // 2*relu
            u64 s1 = add2(x1, x1 & ABSM);
            accp[0][0] = fma2(s0, w.x, accp[0][0]);
            accp[0][1] = fma2(s0, w.y, accp[0][1]);
            accp[1][0] = fma2(s1, w.x, accp[1][0]);
            accp[1][1] = fma2(s1, w.y, accp[1][1]);
        }
        __syncthreads();
    }

    float* __restrict__ pp = g_part + (size_t)hh * PAIR_TOT;
    #pragma unroll
    for (int i = 0; i < 2; i++) {
        float o0t0, o0t1, o1t0, o1t1;
        unpack2(o0t0, o0t1, accp[i][0]);
        unpack2(o1t0, o1t1, accp[i][1]);
        int s = st * 32 + sq * 2 + i;
        int t = tt * 32 + tq * 2;
        size_t idx = (((size_t)batch * SEQ + s) * SEQ + t) * NOUT;
        *(float4*)&pp[idx] = make_float4(o0t0, o1t0, o0t1, o1t1);
    }
}

// ---------------------------------------------------------------------------
// Kernel 3: deterministic combine of the two h-halves + b2.
// ---------------------------------------------------------------------------
__global__ __launch_bounds__(256) void combine_kernel(
    float* __restrict__ out, const float* __restrict__ b2)
{
    int i = blockIdx.x * 256 + threadIdx.x;
    float4 p0 = *(const float4*)&g_part[(size_t)i * 4];
    float4 p1 = *(const float4*)&g_part[(size_t)PAIR_TOT + (size_t)i * 4];
    float c0 = b2[0], c1 = b2[1];
    float4 v = make_float4(p0.x + p1.x + c0, p0.y + p1.y + c1,
                           p0.z + p1.z + c0, p0.w + p1.w + c1);
    *(float4*)&out[(size_t)i * 4] = v;
}

// ---------------------------------------------------------------------------
extern "C" void kernel_launch(void* const* d_in, const int* in_sizes, int n_in,
                              void* d_out, int out_size)
{
    const float* a  = (const float*)d_in[0];
    const float* b  = (const float*)d_in[1];
    const float* W1 = (const float*)d_in[2];
    const float* b1 = (const float*)d_in[3];
    const float* W2 = (const float*)d_in[4];
    const float* b2 = (const float*)d_in[5];
    float* out = (float*)d_out;

    proj_tc<<<dim3(HID / 64, MROWS / 64, 2), 256>>>(a, b, W1, b1);
    pair_kernel<<<dim3(SEQ / 32, SEQ / 32, BS * 2), 256>>>(W2);
    combine_kernel<<<PAIR_TOT / 4 / 256, 256>>>(out, b2);
}

// round 5
// speedup vs baseline: 1.0461x; 1.0461x over previous
#include <cuda_runtime.h>
#include <cstdint>

#define BS   4
#define SEQ  128
#define DIM  768
#define HID  768
#define NOUT 2
#define MROWS (BS * SEQ)                    // 512
#define PAIR_TOT (BS * SEQ * SEQ * NOUT)    // 131072
#define KSPLIT 384                          // K per split-K half

// ---------------- device scratch (no allocation allowed) -------------------
__device__ float g_ar[MROWS * DIM];         // tf32-rounded a
__device__ float g_br[MROWS * DIM];         // tf32-rounded b
__device__ float g_W1r[2 * DIM * HID];      // tf32-rounded W1
__device__ float g_ha[MROWS * HID];         // partial: a @ W1[:D], k-half 0
__device__ float g_hb[MROWS * HID];         // partial: b @ W1[D:] + b1, k-half 0
__device__ float g_ha2[MROWS * HID];        // partial k-half 1
__device__ float g_hb2[MROWS * HID];        // partial k-half 1
__device__ float g_part[2 * PAIR_TOT];      // per-h-half partial scores

// ---------------------------------------------------------------------------
__device__ __forceinline__ uint32_t smem_u32(const void* p) {
    uint32_t a;
    asm("{ .reg .u64 t; cvta.to.shared.u64 t, %1; cvt.u32.u64 %0, t; }"
        : "=r"(a) : "l"(p));
    return a;
}

__device__ __forceinline__ void cp_async16(uint32_t saddr, const void* gptr) {
    asm volatile("cp.async.cg.shared.global [%0], [%1], 16;"
                 :: "r"(saddr), "l"(gptr) : "memory");
}
__device__ __forceinline__ void cp_commit() {
    asm volatile("cp.async.commit_group;" ::: "memory");
}
template <int N>
__device__ __forceinline__ void cp_wait() {
    asm volatile("cp.async.wait_group %0;" :: "n"(N) : "memory");
}

__device__ __forceinline__ float rnd_tf32(float x) {
    uint32_t u;
    asm("cvt.rna.tf32.f32 %0, %1;" : "=r"(u) : "f"(x));
    return __uint_as_float(u);
}

__device__ __forceinline__ void mma_tf32(float* c, const uint32_t* a,
                                         const uint32_t* b) {
    asm volatile(
        "mma.sync.aligned.m16n8k8.row.col.f32.tf32.tf32.f32 "
        "{%0,%1,%2,%3}, {%4,%5,%6,%7}, {%8,%9}, {%0,%1,%2,%3};"
        : "+f"(c[0]), "+f"(c[1]), "+f"(c[2]), "+f"(c[3])
        : "r"(a[0]), "r"(a[1]), "r"(a[2]), "r"(a[3]), "r"(b[0]), "r"(b[1]));
}

// ---------------------------------------------------------------------------
// Kernel 0: round a, b, W1 to tf32-exact fp32 (single fused elementwise pass).
// float4 ranges: a [0,98304), b [98304,196608), W1 [196608,491520).
// ---------------------------------------------------------------------------
__global__ __launch_bounds__(256) void prep_kernel(
    const float* __restrict__ a, const float* __restrict__ b,
    const float* __restrict__ W1)
{
    int i = blockIdx.x * 256 + threadIdx.x;
    const float4* src;
    float4* dst;
    int off;
    if (i < 98304)        { src = (const float4*)a;  dst = (float4*)g_ar;  off = i; }
    else if (i < 196608)  { src = (const float4*)b;  dst = (float4*)g_br;  off = i - 98304; }
    else                  { src = (const float4*)W1; dst = (float4*)g_W1r; off = i - 196608; }
    float4 v = src[off];
    v.x = rnd_tf32(v.x); v.y = rnd_tf32(v.y);
    v.z = rnd_tf32(v.z); v.w = rnd_tf32(v.w);
    dst[off] = v;
}

// ---------------------------------------------------------------------------
// Kernel 1: projection GEMM via mma.sync tf32, split-K=2, no in-loop cvt.
// blockIdx.z: bit0 = z (a/b), bit1 = k-split half.
// CTA tile 64m x 64n, 256 threads (8 warps, warp tile 32x16), K chunk 16,
// 3-stage cp.async pipeline, 24 chunks per CTA. Grid (12, 8, 4) = 384 CTAs.
// ---------------------------------------------------------------------------
#define ALD 20
#define BLD 72

__global__ __launch_bounds__(256) void proj_tc(const float* __restrict__ b1)
{
    __shared__ float As[3][64 * ALD];
    __shared__ float Bs[3][16 * BLD];

    const int tid = threadIdx.x;
    const int wid = tid >> 5;
    const int lane = tid & 31;
    const int r = lane >> 2;            // 0..7
    const int c = lane & 3;             // 0..3
    const int wm = (wid >> 2) * 32;     // warp m base {0,32}
    const int wn = (wid & 3) * 16;      // warp n base {0,16,32,48}

    const int n0 = blockIdx.x * 64;
    const int m0 = blockIdx.y * 64;
    const int z  = blockIdx.z & 1;
    const int kh = blockIdx.z >> 1;     // k-split half
    const int kbase = kh * KSPLIT;

    const float* __restrict__ X = z ? g_br : g_ar;
    const float* __restrict__ W = g_W1r + (size_t)z * DIM * HID;

    const int a_r = tid >> 2;           // 0..63
    const int a_c = (tid & 3) * 4;      // 0..12
    const int b_r = tid >> 4;           // 0..15
    const int b_c = (tid & 15) * 4;     // 0..60

    const uint32_t sA[3] = { smem_u32(As[0]), smem_u32(As[1]), smem_u32(As[2]) };
    const uint32_t sB[3] = { smem_u32(Bs[0]), smem_u32(Bs[1]), smem_u32(Bs[2]) };

    auto ldchunk = [&](int chunk, int s) {
        const int k0 = kbase + chunk * 16;
        cp_async16(sA[s] + (uint32_t)(a_r * ALD + a_c) * 4,
                   X + (size_t)(m0 + a_r) * DIM + k0 + a_c);
        cp_async16(sB[s] + (uint32_t)(b_r * BLD + b_c) * 4,
                   W + (size_t)(k0 + b_r) * HID + n0 + b_c);
        cp_commit();
    };

    float acc[2][2][4] = {};

    ldchunk(0, 0);
    ldchunk(1, 1);

    for (int chunk = 0; chunk < 24; chunk++) {
        const int s = chunk % 3;
        if (chunk + 2 < 24) ldchunk(chunk + 2, (chunk + 2) % 3);

        if (chunk < 22)       cp_wait<2>();
        else if (chunk == 22) cp_wait<1>();
        else                  cp_wait<0>();
        __syncthreads();

        const uint32_t* Ab = (const uint32_t*)As[s];
        const uint32_t* Bb = (const uint32_t*)Bs[s];
        #pragma unroll
        for (int ks = 0; ks < 2; ks++) {
            const int kb = ks * 8;
            uint32_t af[2][4];
            #pragma unroll
            for (int mt = 0; mt < 2; mt++) {
                const uint32_t* ap = Ab + (wm + mt * 16 + r) * ALD + kb + c;
                af[mt][0] = ap[0];
                af[mt][1] = ap[8 * ALD];
                af[mt][2] = ap[4];
                af[mt][3] = ap[8 * ALD + 4];
            }
            uint32_t bf[2][2];
            #pragma unroll
            for (int nt = 0; nt < 2; nt++) {
                const uint32_t* bp = Bb + (kb + c) * BLD + wn + nt * 8 + r;
                bf[nt][0] = bp[0];
                bf[nt][1] = bp[4 * BLD];
            }
            #pragma unroll
            for (int nt = 0; nt < 2; nt++)
                #pragma unroll
                for (int mt = 0; mt < 2; mt++)
                    mma_tf32(acc[mt][nt], af[mt], bf[nt]);
        }
        __syncthreads();
    }

    // epilogue: write per-split partial (+ b1 once, on z=1 k-half 0)
    float* __restrict__ outp = z ? (kh ? g_hb2 : g_hb) : (kh ? g_ha2 : g_ha);
    const bool addb = (z == 1) && (kh == 0);
    #pragma unroll
    for (int mt = 0; mt < 2; mt++) {
        #pragma unroll
        for (int nt = 0; nt < 2; nt++) {
            int m = m0 + wm + mt * 16 + r;
            int n = n0 + wn + nt * 8 + c * 2;
            float2 v0 = make_float2(acc[mt][nt][0], acc[mt][nt][1]);
            float2 v1 = make_float2(acc[mt][nt][2], acc[mt][nt][3]);
            if (addb) {
                float2 bb = *(const float2*)&b1[n];
                v0.x += bb.x; v0.y += bb.y;
                v1.x += bb.x; v1.y += bb.y;
            }
            *(float2*)&outp[(size_t)m * HID + n] = v0;
            *(float2*)&outp[(size_t)(m + 8) * HID + n] = v1;
        }
    }
}

// ---------------------------------------------------------------------------
// Kernel 2: pairwise relu + reduce to O=2 (R3 scalar form; sums the two
// split-K partials while filling shared memory).
// ---------------------------------------------------------------------------
#define HC 64
__global__ __launch_bounds__(256) void pair_kernel(const float* __restrict__ W2)
{
    const int tt = blockIdx.x;
    const int st = blockIdx.y;
    const int zb = blockIdx.z;
    const int batch = zb >> 1;
    const int hh = zb & 1;
    const int h0base = hh * (HID / 2);

    __shared__ float sha[32][HC];
    __shared__ float shT[HC][32];
    __shared__ float sw[HC * 2];

    const int tid = threadIdx.x;
    const int tq = tid & 15;
    const int sq = tid >> 4;

    const size_t rowoff = (size_t)(batch * SEQ + st * 32) * HID;
    const size_t rowoffT = (size_t)(batch * SEQ + tt * 32) * HID;
    const float* __restrict__ hap  = g_ha  + rowoff;
    const float* __restrict__ hap2 = g_ha2 + rowoff;
    const float* __restrict__ hbp  = g_hb  + rowoffT;
    const float* __restrict__ hbp2 = g_hb2 + rowoffT;

    const int lr = tid >> 3;
    const int lc = (tid & 7) * 8;
    const int tr = tid & 31;
    const int th = (tid >> 5) * 8;

    float acc[2][2][2] = {};

    for (int hc = 0; hc < HID / 2; hc += HC) {
        const int h0 = h0base + hc;

        #pragma unroll
        for (int q = 0; q < 2; q++) {
            float4 u  = *(const float4*)&hap [(size_t)lr * HID + h0 + lc + 4 * q];
            float4 u2 = *(const float4*)&hap2[(size_t)lr * HID + h0 + lc + 4 * q];
            u.x += u2.x; u.y += u2.y; u.z += u2.z; u.w += u2.w;
            *(float4*)&sha[lr][lc + 4 * q] = u;
        }

        #pragma unroll
        for (int q = 0; q < 2; q++) {
            float4 v  = *(const float4*)&hbp [(size_t)tr * HID + h0 + th + 4 * q];
            float4 v2 = *(const float4*)&hbp2[(size_t)tr * HID + h0 + th + 4 * q];
            v.x += v2.x; v.y += v2.y; v.z += v2.z; v.w += v2.w;
            shT[th + 4 * q + 0][tr] = v.x;
            shT[th + 4 * q + 1][tr] = v.y;
            shT[th + 4 * q + 2][tr] = v.z;
            shT[th + 4 * q + 3][tr] = v.w;
        }

        if (tid < 32)
            *(float4*)&sw[tid * 4] = *(const float4*)&W2[h0 * 2 + tid * 4];
        __syncthreads();

        #pragma unroll 16
        for (int h = 0; h < HC; h++) {
            float a0 = sha[sq * 2][h];
            float a1 = sha[sq * 2 + 1][h];
            float2 bb = *(const float2*)&shT[h][tq * 2];
            float2 wv = *(const float2*)&sw[h * 2];
            float r;
            r = fmaxf(a0 + bb.x, 0.f); acc[0][0][0] += r * wv.x; acc[0][0][1] += r * wv.y;
            r = fmaxf(a0 + bb.y, 0.f); acc[0][1][0] += r * wv.x; acc[0][1][1] += r * wv.y;
            r = fmaxf(a1 + bb.x, 0.f); acc[1][0][0] += r * wv.x; acc[1][0][1] += r * wv.y;
            r = fmaxf(a1 + bb.y, 0.f); acc[1][1][0] += r * wv.x; acc[1][1][1] += r * wv.y;
        }
        __syncthreads();
    }

    float* __restrict__ pp = g_part + (size_t)hh * PAIR_TOT;
    #pragma unroll
    for (int i = 0; i < 2; i++) {
        #pragma unroll
        for (int j = 0; j < 2; j++) {
            int s = st * 32 + sq * 2 + i;
            int t = tt * 32 + tq * 2 + j;
            size_t idx = (((size_t)batch * SEQ + s) * SEQ + t) * NOUT;
            *(float2*)&pp[idx] = make_float2(acc[i][j][0], acc[i][j][1]);
        }
    }
}

// ---------------------------------------------------------------------------
// Kernel 3: deterministic combine of the two h-halves + b2.
// ---------------------------------------------------------------------------
__global__ __launch_bounds__(256) void combine_kernel(
    float* __restrict__ out, const float* __restrict__ b2)
{
    int i = blockIdx.x * 256 + threadIdx.x;
    float4 p0 = *(const float4*)&g_part[(size_t)i * 4];
    float4 p1 = *(const float4*)&g_part[(size_t)PAIR_TOT + (size_t)i * 4];
    float c0 = b2[0], c1 = b2[1];
    float4 v = make_float4(p0.x + p1.x + c0, p0.y + p1.y + c1,
                           p0.z + p1.z + c0, p0.w + p1.w + c1);
    *(float4*)&out[(size_t)i * 4] = v;
}

// ---------------------------------------------------------------------------
extern "C" void kernel_launch(void* const* d_in, const int* in_sizes, int n_in,
                              void* d_out, int out_size)
{
    const float* a  = (const float*)d_in[0];
    const float* b  = (const float*)d_in[1];
    const float* W1 = (const float*)d_in[2];
    const float* b1 = (const float*)d_in[3];
    const float* W2 = (const float*)d_in[4];
    const float* b2 = (const float*)d_in[5];
    float* out = (float*)d_out;

    prep_kernel<<<1920, 256>>>(a, b, W1);
    proj_tc<<<dim3(HID / 64, MROWS / 64, 4), 256>>>(b1);
    pair_kernel<<<dim3(SEQ / 32, SEQ / 32, BS * 2), 256>>>(W2);
    combine_kernel<<<PAIR_TOT / 4 / 256, 256>>>(out, b2);
}